// round 14
// baseline (speedup 1.0000x reference)
#include <cuda_runtime.h>
#include <cuda_bf16.h>
#include <cstdint>

#define BATCH 4
#define MPER  4096
#define NTOT  (BATCH * MPER)
#define PAD_I (-999)
#define PAD_F (-999.0f)
#define CUT2  49.0f

#define JSPLIT 64
#define JCHUNK (MPER / JSPLIT)        // 64 j's per chunk = 32 packed jj's
#define PT_THREADS 128
#define RPT 4
#define ROWS_PER_BLOCK (PT_THREADS * RPT)   // 512
#define NRB (NTOT / ROWS_PER_BLOCK)         // 32 row-blocks
#define NPAIRB (NRB * JSPLIT)               // 2048 pair blocks
#define NTAILB (NTOT / PT_THREADS)          // 128 tail blocks
#define NBLOCKS (NTAILB + NPAIRB)           // 2176

// Partial row-sums: [JSPLIT][NTOT]  (4 MB)
__device__ float g_partial[JSPLIT * NTOT];
// Arrival counters, one per row-block (zero-init; reset by the reducing block)
__device__ int g_ctr[NRB];

// ---------------- packed f32x2 helpers (Blackwell) -------------------------
__device__ __forceinline__ uint64_t pk2(float f) {
    uint64_t r; uint32_t u = __float_as_uint(f);
    asm("mov.b64 %0, {%1, %1};" : "=l"(r) : "r"(u));
    return r;
}
__device__ __forceinline__ uint64_t pfma(uint64_t a, uint64_t b, uint64_t c) {
    uint64_t r;
    asm("fma.rn.f32x2 %0, %1, %2, %3;" : "=l"(r) : "l"(a), "l"(b), "l"(c));
    return r;
}
__device__ __forceinline__ float lo32(uint64_t v) {
    return __uint_as_float((uint32_t)v);
}

__device__ __forceinline__ float3 f3sub(float3 a, float3 b) {
    return make_float3(a.x - b.x, a.y - b.y, a.z - b.z);
}
__device__ __forceinline__ float3 f3cross(float3 a, float3 b) {
    return make_float3(a.y * b.z - a.z * b.y,
                       a.z * b.x - a.x * b.z,
                       a.x * b.y - a.y * b.x);
}
__device__ __forceinline__ float f3dot(float3 a, float3 b) {
    return a.x * b.x + a.y * b.y + a.z * b.z;
}
__device__ __forceinline__ float3 gat3(const float* __restrict__ coords,
                                       const int* __restrict__ abatch,
                                       const int* __restrict__ cidx, int n) {
    const float* p = coords + ((long)abatch[n] * MPER + cidx[n]) * 3;
    return make_float3(p[0], p[1], p[2]);
}

// ---------------------------------------------------------------------------
// One kernel, two block roles:
//   blocks [0, 128): tails — dihedral (col 0) + partner cols (2..7), 1 row/thread
//   blocks [128, 2176): pair screening, 32 row-blocks x 64 j-chunks
// ---------------------------------------------------------------------------
__global__ void __launch_bounds__(PT_THREADS)
ff_all(const float* __restrict__ coords,
       const int*   __restrict__ abatch,
       const int*   __restrict__ cidx,
       const int*   __restrict__ partners,
       const int*   __restrict__ aidx,
       float*       __restrict__ out) {
    int tid = threadIdx.x;

    // ================= Tail blocks =================
    if (blockIdx.x < NTAILB) {
        int i = blockIdx.x * PT_THREADS + tid;

        // partner columns -> out cols 2..7
        int pb = abatch[i];
        #pragma unroll
        for (int k = 0; k < 2; k++) {
            int p = partners[i * 2 + k];
            float px, py, pz;
            if (p == PAD_I) {
                px = PAD_F; py = PAD_F; pz = PAD_F;
            } else {
                const float* pp = coords + ((long)pb * MPER + p) * 3;
                px = pp[0]; py = pp[1]; pz = pp[2];
            }
            float* o = out + (long)i * 8 + 2 + 3 * k;
            o[0] = px; o[1] = py; o[2] = pz;
        }

        // dihedral -> out col 0
        int i0 = aidx[i * 4 + 0];
        int i1 = aidx[i * 4 + 1];
        int i2 = aidx[i * 4 + 2];
        int i3 = aidx[i * 4 + 3];
        if (i0 == PAD_I || i1 == PAD_I || i2 == PAD_I || i3 == PAD_I) {
            out[(long)i * 8] = PAD_F;
        } else {
            float3 p1 = gat3(coords, abatch, cidx, i0);
            float3 p2 = gat3(coords, abatch, cidx, i1);
            float3 p3 = gat3(coords, abatch, cidx, i2);
            float3 p4 = gat3(coords, abatch, cidx, i3);
            float3 b1 = f3sub(p2, p1);
            float3 b2 = f3sub(p3, p2);
            float3 b3 = f3sub(p4, p3);
            float3 n1 = f3cross(b1, b2);
            float3 n2 = f3cross(b2, b3);
            float nb2 = sqrtf((b2.x * b2.x + b2.y * b2.y) + b2.z * b2.z);
            float inv = 1.0f / (nb2 + 1e-12f);
            float3 b2n = make_float3(b2.x * inv, b2.y * inv, b2.z * inv);
            float3 m1 = f3cross(n1, b2n);
            out[(long)i * 8] = atan2f(f3dot(m1, n2), f3dot(n1, n2));
        }
        return;
    }

    // ================= Pair blocks =================
    // 2 float4 per packed jj: [x0 x1 y0 y1][z0 z1 w0-49 w1-49]
    __shared__ float4 sh[2 * (JCHUNK / 2)];
    __shared__ int s_last;

    int pbk = blockIdx.x - NTAILB;
    int rb = pbk >> 6;                 // row-block 0..31
    int jc = pbk & 63;                 // j-chunk  0..63
    int b  = rb >> 3;                  // 8 row-blocks per batch
    int jbase = b * MPER + jc * JCHUNK;

    // ---- self-gather j-tile (32 packed slots) ----
    if (tid < JCHUNK / 2) {
        int n0 = jbase + 2 * tid;
        int2 bb = *(const int2*)(abatch + n0);
        int2 cc = *(const int2*)(cidx + n0);
        const float* p0 = coords + ((long)bb.x * MPER + cc.x) * 3;
        const float* p1 = coords + ((long)bb.y * MPER + cc.y) * 3;
        float x0 = p0[0], y0 = p0[1], z0 = p0[2];
        float x1 = p1[0], y1 = p1[1], z1 = p1[2];
        float w0 = (x0 != PAD_F) ? (x0 * x0 + y0 * y0) + z0 * z0 : 3e30f;
        float w1 = (x1 != PAD_F) ? (x1 * x1 + y1 * y1) + z1 * z1 : 3e30f;
        sh[2 * tid]     = make_float4(x0, x1, y0, y1);
        sh[2 * tid + 1] = make_float4(z0, z1, w0 - CUT2, w1 - CUT2);
    }

    // ---- 4 i-rows to packed registers ----
    int row0 = rb * ROWS_PER_BLOCK + tid;
    float    sum[RPT];
    uint64_t mx[RPT], my2[RPT], mz2[RPT], mh[RPT];
    #pragma unroll
    for (int k = 0; k < RPT; k++) {
        int r = row0 + k * PT_THREADS;
        const float* p = coords + ((long)abatch[r] * MPER + cidx[r]) * 3;
        float x = p[0], y = p[1], z = p[2];
        float sq = (x != PAD_F) ? (x * x + y * y) + z * z : 3e30f;
        sum[k] = 0.0f;
        mx[k]  = pk2(x);
        my2[k] = pk2(y);
        mz2[k] = pk2(z);
        mh[k]  = pk2(-0.5f * sq);      // seed: dot - sq_i/2
    }
    const uint64_t NEG2 = pk2(-2.0f);
    const uint32_t sb   = (uint32_t)__cvta_generic_to_shared(sh);
    __syncthreads();

    // ---- screening (packed f32x2) + per-thread bitmask replay ----
    uint32_t mask = 0;
    #pragma unroll 4
    for (int jj = 0; jj < 32; jj++) {
        uint32_t ad = sb + (uint32_t)jj * 32u;
        uint64_t ux, uy, uz, uw;
        asm("ld.shared.v2.u64 {%0, %1}, [%2];"
            : "=l"(ux), "=l"(uy) : "r"(ad));
        asm("ld.shared.v2.u64 {%0, %1}, [%2];"
            : "=l"(uz), "=l"(uw) : "r"(ad + 16u));
        uint32_t orr = 0;
        #pragma unroll
        for (int k = 0; k < RPT; k++) {
            uint64_t t = pfma(mz2[k], uz, mh[k]);
            t = pfma(my2[k], uy, t);
            t = pfma(mx[k],  ux, t);
            uint64_t s = pfma(NEG2, t, uw);   // D - 49, packed x2
            orr |= (uint32_t)s | (uint32_t)(s >> 32);
        }
        mask = (mask << 1) | (orr >> 31);
    }
    while (mask) {
        int jjl = __clz(mask);
        mask &= ~(0x80000000u >> jjl);
        float4 A  = sh[2 * jjl];       // x0 x1 y0 y1
        float4 Bv = sh[2 * jjl + 1];   // z0 z1 w0-49 w1-49
        float w0 = Bv.z + CUT2;        // exact round-trip
        float w1 = Bv.w + CUT2;
        #pragma unroll
        for (int k = 0; k < RPT; k++) {
            float x  = lo32(mx[k]);
            float y  = lo32(my2[k]);
            float z  = lo32(mz2[k]);
            float sq = -2.0f * lo32(mh[k]);    // exact
            float cmp = CUT2 - sq;

            float t0 = z * Bv.x;
            t0 = fmaf(y, A.z, t0);
            t0 = fmaf(x, A.x, t0);
            float d20 = fmaf(-2.0f, t0, w0);
            if (d20 <= cmp)
                sum[k] += sqrtf(fmaxf(d20 + sq, 0.0f) + 1e-12f);

            float t1 = z * Bv.y;
            t1 = fmaf(y, A.w, t1);
            t1 = fmaf(x, A.y, t1);
            float d21 = fmaf(-2.0f, t1, w1);
            if (d21 <= cmp)
                sum[k] += sqrtf(fmaxf(d21 + sq, 0.0f) + 1e-12f);
        }
    }

    #pragma unroll
    for (int k = 0; k < RPT; k++)
        g_partial[jc * NTOT + row0 + k * PT_THREADS] = sum[k];

    // ---- last-block reduction per row-block ----
    __threadfence();               // make partials visible GPU-wide
    __syncthreads();
    if (tid == 0)
        s_last = (atomicAdd(&g_ctr[rb], 1) == JSPLIT - 1);
    __syncthreads();
    if (s_last) {
        int base = rb * ROWS_PER_BLOCK;
        #pragma unroll
        for (int q = 0; q < RPT; q++) {
            int row = base + tid + q * PT_THREADS;
            float s = 0.0f;
            #pragma unroll
            for (int c = 0; c < JSPLIT; c++)
                s += __ldcg(&g_partial[c * NTOT + row]);
            out[(long)row * 8 + 1] = s;
        }
        if (tid == 0) g_ctr[rb] = 0;   // reset for next graph replay
    }
}

// ---------------------------------------------------------------------------
extern "C" void kernel_launch(void* const* d_in, const int* in_sizes, int n_in,
                              void* d_out, int out_size) {
    const float* coords   = (const float*)d_in[0];
    const int*   abatch   = (const int*)  d_in[1];
    const int*   cidx     = (const int*)  d_in[2];
    const int*   partners = (const int*)  d_in[3];
    const int*   aidx     = (const int*)  d_in[4];
    float*       out      = (float*)d_out;

    ff_all<<<NBLOCKS, PT_THREADS>>>(coords, abatch, cidx, partners, aidx, out);
}

// round 15
// speedup vs baseline: 1.2060x; 1.2060x over previous
#include <cuda_runtime.h>
#include <cuda_bf16.h>
#include <cstdint>

#define BATCH 4
#define MPER  4096
#define NTOT  (BATCH * MPER)
#define PAD_I (-999)
#define PAD_F (-999.0f)
#define CUT2  49.0f

#define PT_THREADS 128
#define RPT 4
#define ROWS_PER_BLOCK (PT_THREADS * RPT)   // 512
#define RPB 8                                // row-blocks per batch
#define CPB 64                               // j-chunks (of 64) per batch
#define TILES_PER_BATCH 288                  // sum_{r=0..7} (8r+8)
#define NPAIRB (BATCH * TILES_PER_BATCH)     // 1152
#define NTAILB (NTOT / PT_THREADS)           // 128
#define NBLOCKS (NTAILB + NPAIRB)            // 1280

// i-side partials: [c][global row]  (4 MB)
__device__ float g_ip[CPB * NTOT];
// j-side partials: [r][global j]    (512 KB)
__device__ float g_jp[RPB * NTOT];

// ---------------- packed f32x2 helpers (Blackwell) -------------------------
__device__ __forceinline__ uint64_t pk2(float f) {
    uint64_t r; uint32_t u = __float_as_uint(f);
    asm("mov.b64 %0, {%1, %1};" : "=l"(r) : "r"(u));
    return r;
}
__device__ __forceinline__ uint64_t pfma(uint64_t a, uint64_t b, uint64_t c) {
    uint64_t r;
    asm("fma.rn.f32x2 %0, %1, %2, %3;" : "=l"(r) : "l"(a), "l"(b), "l"(c));
    return r;
}
__device__ __forceinline__ float lo32(uint64_t v) {
    return __uint_as_float((uint32_t)v);
}

__device__ __forceinline__ float3 f3sub(float3 a, float3 b) {
    return make_float3(a.x - b.x, a.y - b.y, a.z - b.z);
}
__device__ __forceinline__ float3 f3cross(float3 a, float3 b) {
    return make_float3(a.y * b.z - a.z * b.y,
                       a.z * b.x - a.x * b.z,
                       a.x * b.y - a.y * b.x);
}
__device__ __forceinline__ float f3dot(float3 a, float3 b) {
    return a.x * b.x + a.y * b.y + a.z * b.z;
}
__device__ __forceinline__ float3 gat3(const float* __restrict__ coords,
                                       const int* __restrict__ abatch,
                                       const int* __restrict__ cidx, int n) {
    const float* p = coords + ((long)abatch[n] * MPER + cidx[n]) * 3;
    return make_float3(p[0], p[1], p[2]);
}

// ---------------------------------------------------------------------------
// Kernel 1: tails (blocks 0..127) + triangular pair tiles (blocks 128..1279)
// ---------------------------------------------------------------------------
__global__ void __launch_bounds__(PT_THREADS)
ff_main(const float* __restrict__ coords,
        const int*   __restrict__ abatch,
        const int*   __restrict__ cidx,
        const int*   __restrict__ partners,
        const int*   __restrict__ aidx,
        float*       __restrict__ out) {
    int tid = threadIdx.x;

    // ================= Tail blocks =================
    if (blockIdx.x < NTAILB) {
        int i = blockIdx.x * PT_THREADS + tid;

        int pb = abatch[i];
        #pragma unroll
        for (int k = 0; k < 2; k++) {
            int p = partners[i * 2 + k];
            float px, py, pz;
            if (p == PAD_I) {
                px = PAD_F; py = PAD_F; pz = PAD_F;
            } else {
                const float* pp = coords + ((long)pb * MPER + p) * 3;
                px = pp[0]; py = pp[1]; pz = pp[2];
            }
            float* o = out + (long)i * 8 + 2 + 3 * k;
            o[0] = px; o[1] = py; o[2] = pz;
        }

        int i0 = aidx[i * 4 + 0];
        int i1 = aidx[i * 4 + 1];
        int i2 = aidx[i * 4 + 2];
        int i3 = aidx[i * 4 + 3];
        if (i0 == PAD_I || i1 == PAD_I || i2 == PAD_I || i3 == PAD_I) {
            out[(long)i * 8] = PAD_F;
        } else {
            float3 p1 = gat3(coords, abatch, cidx, i0);
            float3 p2 = gat3(coords, abatch, cidx, i1);
            float3 p3 = gat3(coords, abatch, cidx, i2);
            float3 p4 = gat3(coords, abatch, cidx, i3);
            float3 b1 = f3sub(p2, p1);
            float3 b2 = f3sub(p3, p2);
            float3 b3 = f3sub(p4, p3);
            float3 n1 = f3cross(b1, b2);
            float3 n2 = f3cross(b2, b3);
            float nb2 = sqrtf((b2.x * b2.x + b2.y * b2.y) + b2.z * b2.z);
            float inv = 1.0f / (nb2 + 1e-12f);
            float3 b2n = make_float3(b2.x * inv, b2.y * inv, b2.z * inv);
            float3 m1 = f3cross(n1, b2n);
            out[(long)i * 8] = atan2f(f3dot(m1, n2), f3dot(n1, n2));
        }
        return;
    }

    // ================= Pair tiles (lower triangle incl. diagonal band) =====
    __shared__ float4 sh[64];          // 2 float4 per packed jj (32 jj)
    __shared__ float  shj[64];         // j-side accumulators

    int q = blockIdx.x - NTAILB;
    int batch = q / TILES_PER_BATCH;
    q -= batch * TILES_PER_BATCH;
    int r = 0;
    while (q >= 8 * r + 8) { q -= 8 * r + 8; r++; }   // uniform, <=8 iters
    int c = q;                          // tile (r, c), c <= 8r+7
    bool diag = (c >= 8 * r);           // diagonal band: need i>j filter
    int jbase = batch * MPER + c * 64;  // global j start
    int jloc_base = c * 64;             // local-to-batch j start

    // ---- gather j-tile (32 packed slots) + init shj ----
    if (tid < 32) {
        int n0 = jbase + 2 * tid;
        int2 bb = *(const int2*)(abatch + n0);
        int2 cc = *(const int2*)(cidx + n0);
        const float* p0 = coords + ((long)bb.x * MPER + cc.x) * 3;
        const float* p1 = coords + ((long)bb.y * MPER + cc.y) * 3;
        float x0 = p0[0], y0 = p0[1], z0 = p0[2];
        float x1 = p1[0], y1 = p1[1], z1 = p1[2];
        float w0 = (x0 != PAD_F) ? (x0 * x0 + y0 * y0) + z0 * z0 : 3e30f;
        float w1 = (x1 != PAD_F) ? (x1 * x1 + y1 * y1) + z1 * z1 : 3e30f;
        sh[2 * tid]     = make_float4(x0, x1, y0, y1);
        sh[2 * tid + 1] = make_float4(z0, z1, w0 - CUT2, w1 - CUT2);
    }
    if (tid < 64) shj[tid] = 0.0f;

    // ---- 4 i-rows to packed registers ----
    int row0g = batch * MPER + r * ROWS_PER_BLOCK + tid;   // global
    int iloc0 = r * ROWS_PER_BLOCK + tid;                  // local-to-batch
    float    sum[RPT];
    uint64_t mx[RPT], my2[RPT], mz2[RPT], mh[RPT];
    #pragma unroll
    for (int k = 0; k < RPT; k++) {
        int rr = row0g + k * PT_THREADS;
        const float* p = coords + ((long)abatch[rr] * MPER + cidx[rr]) * 3;
        float x = p[0], y = p[1], z = p[2];
        float sq = (x != PAD_F) ? (x * x + y * y) + z * z : 3e30f;
        sum[k] = 0.0f;
        mx[k]  = pk2(x);
        my2[k] = pk2(y);
        mz2[k] = pk2(z);
        mh[k]  = pk2(-0.5f * sq);      // seed: dot - sq_i/2
    }
    const uint64_t NEG2 = pk2(-2.0f);
    const uint32_t sb   = (uint32_t)__cvta_generic_to_shared(sh);
    __syncthreads();

    // ---- screening (packed f32x2) + per-thread bitmask replay ----
    uint32_t mask = 0;
    #pragma unroll 4
    for (int jj = 0; jj < 32; jj++) {
        uint32_t ad = sb + (uint32_t)jj * 32u;
        uint64_t ux, uy, uz, uw;
        asm("ld.shared.v2.u64 {%0, %1}, [%2];"
            : "=l"(ux), "=l"(uy) : "r"(ad));
        asm("ld.shared.v2.u64 {%0, %1}, [%2];"
            : "=l"(uz), "=l"(uw) : "r"(ad + 16u));
        uint32_t orr = 0;
        #pragma unroll
        for (int k = 0; k < RPT; k++) {
            uint64_t t = pfma(mz2[k], uz, mh[k]);
            t = pfma(my2[k], uy, t);
            t = pfma(mx[k],  ux, t);
            uint64_t s = pfma(NEG2, t, uw);   // D - 49, packed x2
            orr |= (uint32_t)s | (uint32_t)(s >> 32);
        }
        mask = (mask << 1) | (orr >> 31);
    }
    while (mask) {
        int jjl = __clz(mask);
        mask &= ~(0x80000000u >> jjl);
        float4 A  = sh[2 * jjl];       // x0 x1 y0 y1
        float4 Bv = sh[2 * jjl + 1];   // z0 z1 w0-49 w1-49
        float w0 = Bv.z + CUT2;        // exact round-trip
        float w1 = Bv.w + CUT2;
        int jl0 = jloc_base + 2 * jjl;
        #pragma unroll
        for (int k = 0; k < RPT; k++) {
            float x  = lo32(mx[k]);
            float y  = lo32(my2[k]);
            float z  = lo32(mz2[k]);
            float sq = -2.0f * lo32(mh[k]);    // exact
            float cmp = CUT2 - sq;
            int iloc = iloc0 + k * PT_THREADS;

            float t0 = z * Bv.x;
            t0 = fmaf(y, A.z, t0);
            t0 = fmaf(x, A.x, t0);
            float d20 = fmaf(-2.0f, t0, w0);
            if (d20 <= cmp && (!diag || iloc > jl0)) {
                float d = sqrtf(fmaxf(d20 + sq, 0.0f) + 1e-12f);
                sum[k] += d;
                atomicAdd(&shj[2 * jjl], d);
            }

            float t1 = z * Bv.y;
            t1 = fmaf(y, A.w, t1);
            t1 = fmaf(x, A.y, t1);
            float d21 = fmaf(-2.0f, t1, w1);
            if (d21 <= cmp && (!diag || iloc > jl0 + 1)) {
                float d = sqrtf(fmaxf(d21 + sq, 0.0f) + 1e-12f);
                sum[k] += d;
                atomicAdd(&shj[2 * jjl + 1], d);
            }
        }
    }

    // ---- write partials ----
    #pragma unroll
    for (int k = 0; k < RPT; k++)
        g_ip[c * NTOT + row0g + k * PT_THREADS] = sum[k];
    __syncthreads();                   // shj atomics complete
    if (tid < 64)
        g_jp[r * NTOT + jbase + tid] = shj[tid];
}

// ---------------------------------------------------------------------------
// Kernel 2: deterministic reduce -> out col 1
//   row i (local loc, row-block r = loc>>9): sum i-side tiles c=0..8r+7,
//   j-side tiles r'=r..7, plus self term sqrt(1e-12) if valid.
// ---------------------------------------------------------------------------
__global__ void __launch_bounds__(PT_THREADS)
ff_reduce(const float* __restrict__ coords,
          const int*   __restrict__ abatch,
          const int*   __restrict__ cidx,
          float*       __restrict__ out) {
    int i = blockIdx.x * PT_THREADS + threadIdx.x;
    int loc = i & (MPER - 1);
    int r = loc >> 9;

    float s = 0.0f;
    int cmax = 8 * r + 8;
    #pragma unroll 8
    for (int c = 0; c < cmax; c++)
        s += g_ip[c * NTOT + i];
    #pragma unroll
    for (int rp = 7; rp >= 0; rp--)       // fixed structure; gate on rp>=r
        if (rp >= r) s += g_jp[rp * NTOT + i];

    const float* p = coords + ((long)abatch[i] * MPER + cidx[i]) * 3;
    if (p[0] != PAD_F) s += sqrtf(1e-12f);   // self pair (i==i)
    else               s = 0.0f;             // invalid row: empty sum

    out[(long)i * 8 + 1] = s;
}

// ---------------------------------------------------------------------------
extern "C" void kernel_launch(void* const* d_in, const int* in_sizes, int n_in,
                              void* d_out, int out_size) {
    const float* coords   = (const float*)d_in[0];
    const int*   abatch   = (const int*)  d_in[1];
    const int*   cidx     = (const int*)  d_in[2];
    const int*   partners = (const int*)  d_in[3];
    const int*   aidx     = (const int*)  d_in[4];
    float*       out      = (float*)d_out;

    ff_main<<<NBLOCKS, PT_THREADS>>>(coords, abatch, cidx, partners, aidx, out);
    ff_reduce<<<NTOT / PT_THREADS, PT_THREADS>>>(coords, abatch, cidx, out);
}

// round 17
// speedup vs baseline: 1.2764x; 1.0583x over previous
#include <cuda_runtime.h>
#include <cuda_bf16.h>
#include <cstdint>

#define BATCH 4
#define MPER  4096
#define NTOT  (BATCH * MPER)
#define PAD_I (-999)
#define PAD_F (-999.0f)
#define CUT2  49.0f

#define PT_THREADS 128
#define RPT 4
#define ROWS_PER_BLOCK (PT_THREADS * RPT)   // 512
#define RPB 8                                // row-blocks per batch
#define CPB 64                               // j-chunks (of 64) per batch
#define TILES_PER_BATCH 288                  // sum_{r=0..7} (8r+8)
#define NPAIRB (BATCH * TILES_PER_BATCH)     // 1152
#define NTAILB (NTOT / PT_THREADS)           // 128
#define NBLOCKS (NTAILB + NPAIRB)            // 1280

// i-side partials: [c][global row]  (4 MB)
__device__ float g_ip[CPB * NTOT];
// j-side partials: [r][global j]    (512 KB)
__device__ float g_jp[RPB * NTOT];

// ---------------- packed f32x2 helpers (Blackwell) -------------------------
__device__ __forceinline__ uint64_t pk2(float f) {
    uint64_t r; uint32_t u = __float_as_uint(f);
    asm("mov.b64 %0, {%1, %1};" : "=l"(r) : "r"(u));
    return r;
}
__device__ __forceinline__ uint64_t pfma(uint64_t a, uint64_t b, uint64_t c) {
    uint64_t r;
    asm("fma.rn.f32x2 %0, %1, %2, %3;" : "=l"(r) : "l"(a), "l"(b), "l"(c));
    return r;
}
__device__ __forceinline__ float lo32(uint64_t v) {
    return __uint_as_float((uint32_t)v);
}

__device__ __forceinline__ float3 f3sub(float3 a, float3 b) {
    return make_float3(a.x - b.x, a.y - b.y, a.z - b.z);
}
__device__ __forceinline__ float3 f3cross(float3 a, float3 b) {
    return make_float3(a.y * b.z - a.z * b.y,
                       a.z * b.x - a.x * b.z,
                       a.x * b.y - a.y * b.x);
}
__device__ __forceinline__ float f3dot(float3 a, float3 b) {
    return a.x * b.x + a.y * b.y + a.z * b.z;
}
__device__ __forceinline__ float3 gat3(const float* __restrict__ coords,
                                       const int* __restrict__ abatch,
                                       const int* __restrict__ cidx, int n) {
    const float* p = coords + ((long)abatch[n] * MPER + cidx[n]) * 3;
    return make_float3(p[0], p[1], p[2]);
}

// ---------------------------------------------------------------------------
// Kernel 1: tails (blocks 0..127) + triangular pair tiles (blocks 128..1279)
// ---------------------------------------------------------------------------
__global__ void __launch_bounds__(PT_THREADS)
ff_main(const float* __restrict__ coords,
        const int*   __restrict__ abatch,
        const int*   __restrict__ cidx,
        const int*   __restrict__ partners,
        const int*   __restrict__ aidx,
        float*       __restrict__ out) {
    int tid = threadIdx.x;

    // ================= Tail blocks =================
    if (blockIdx.x < NTAILB) {
        int i = blockIdx.x * PT_THREADS + tid;

        int pb = abatch[i];
        #pragma unroll
        for (int k = 0; k < 2; k++) {
            int p = partners[i * 2 + k];
            float px, py, pz;
            if (p == PAD_I) {
                px = PAD_F; py = PAD_F; pz = PAD_F;
            } else {
                const float* pp = coords + ((long)pb * MPER + p) * 3;
                px = pp[0]; py = pp[1]; pz = pp[2];
            }
            float* o = out + (long)i * 8 + 2 + 3 * k;
            o[0] = px; o[1] = py; o[2] = pz;
        }

        int i0 = aidx[i * 4 + 0];
        int i1 = aidx[i * 4 + 1];
        int i2 = aidx[i * 4 + 2];
        int i3 = aidx[i * 4 + 3];
        if (i0 == PAD_I || i1 == PAD_I || i2 == PAD_I || i3 == PAD_I) {
            out[(long)i * 8] = PAD_F;
        } else {
            float3 p1 = gat3(coords, abatch, cidx, i0);
            float3 p2 = gat3(coords, abatch, cidx, i1);
            float3 p3 = gat3(coords, abatch, cidx, i2);
            float3 p4 = gat3(coords, abatch, cidx, i3);
            float3 b1 = f3sub(p2, p1);
            float3 b2 = f3sub(p3, p2);
            float3 b3 = f3sub(p4, p3);
            float3 n1 = f3cross(b1, b2);
            float3 n2 = f3cross(b2, b3);
            float nb2 = sqrtf((b2.x * b2.x + b2.y * b2.y) + b2.z * b2.z);
            float inv = 1.0f / (nb2 + 1e-12f);
            float3 b2n = make_float3(b2.x * inv, b2.y * inv, b2.z * inv);
            float3 m1 = f3cross(n1, b2n);
            out[(long)i * 8] = atan2f(f3dot(m1, n2), f3dot(n1, n2));
        }
        return;
    }

    // ================= Pair tiles (lower triangle incl. diagonal band) =====
    __shared__ float4 sh[64];          // 2 float4 per packed jj (32 jj)
    __shared__ float  shj[64];         // j-side accumulators

    int q = blockIdx.x - NTAILB;
    int batch = q / TILES_PER_BATCH;
    q -= batch * TILES_PER_BATCH;
    int r = 0;
    while (q >= 8 * r + 8) { q -= 8 * r + 8; r++; }   // uniform, <=8 iters
    int c = q;                          // tile (r, c), c <= 8r+7
    bool diag = (c >= 8 * r);           // diagonal band: need i>j filter
    int jbase = batch * MPER + c * 64;  // global j start
    int jloc_base = c * 64;             // local-to-batch j start

    // ---- gather j-tile (32 packed slots) + init shj ----
    if (tid < 32) {
        int n0 = jbase + 2 * tid;
        int2 bb = *(const int2*)(abatch + n0);
        int2 cc = *(const int2*)(cidx + n0);
        const float* p0 = coords + ((long)bb.x * MPER + cc.x) * 3;
        const float* p1 = coords + ((long)bb.y * MPER + cc.y) * 3;
        float x0 = p0[0], y0 = p0[1], z0 = p0[2];
        float x1 = p1[0], y1 = p1[1], z1 = p1[2];
        float w0 = (x0 != PAD_F) ? (x0 * x0 + y0 * y0) + z0 * z0 : 3e30f;
        float w1 = (x1 != PAD_F) ? (x1 * x1 + y1 * y1) + z1 * z1 : 3e30f;
        sh[2 * tid]     = make_float4(x0, x1, y0, y1);
        sh[2 * tid + 1] = make_float4(z0, z1, w0 - CUT2, w1 - CUT2);
    }
    if (tid < 64) shj[tid] = 0.0f;

    // ---- 4 i-rows to packed registers ----
    int row0g = batch * MPER + r * ROWS_PER_BLOCK + tid;   // global
    int iloc0 = r * ROWS_PER_BLOCK + tid;                  // local-to-batch
    float    sum[RPT];
    uint64_t mx[RPT], my2[RPT], mz2[RPT], mh[RPT];
    #pragma unroll
    for (int k = 0; k < RPT; k++) {
        int rr = row0g + k * PT_THREADS;
        const float* p = coords + ((long)abatch[rr] * MPER + cidx[rr]) * 3;
        float x = p[0], y = p[1], z = p[2];
        float sq = (x != PAD_F) ? (x * x + y * y) + z * z : 3e30f;
        sum[k] = 0.0f;
        mx[k]  = pk2(x);
        my2[k] = pk2(y);
        mz2[k] = pk2(z);
        mh[k]  = pk2(-0.5f * sq);      // seed: dot - sq_i/2
    }
    const uint64_t NEG2 = pk2(-2.0f);
    const uint32_t sb   = (uint32_t)__cvta_generic_to_shared(sh);
    __syncthreads();

    // ---- screening (packed f32x2) + per-thread bitmask replay ----
    uint32_t mask = 0;
    #pragma unroll 4
    for (int jj = 0; jj < 32; jj++) {
        uint32_t ad = sb + (uint32_t)jj * 32u;
        uint64_t ux, uy, uz, uw;
        asm("ld.shared.v2.u64 {%0, %1}, [%2];"
            : "=l"(ux), "=l"(uy) : "r"(ad));
        asm("ld.shared.v2.u64 {%0, %1}, [%2];"
            : "=l"(uz), "=l"(uw) : "r"(ad + 16u));
        uint32_t orr = 0;
        #pragma unroll
        for (int k = 0; k < RPT; k++) {
            uint64_t t = pfma(mz2[k], uz, mh[k]);
            t = pfma(my2[k], uy, t);
            t = pfma(mx[k],  ux, t);
            uint64_t s = pfma(NEG2, t, uw);   // D - 49, packed x2
            orr |= (uint32_t)s | (uint32_t)(s >> 32);
        }
        mask = (mask << 1) | (orr >> 31);
    }
    while (mask) {
        int jjl = __clz(mask);
        mask &= ~(0x80000000u >> jjl);
        float4 A  = sh[2 * jjl];       // x0 x1 y0 y1
        float4 Bv = sh[2 * jjl + 1];   // z0 z1 w0-49 w1-49
        float w0 = Bv.z + CUT2;        // exact round-trip
        float w1 = Bv.w + CUT2;
        int jl0 = jloc_base + 2 * jjl;
        #pragma unroll
        for (int k = 0; k < RPT; k++) {
            float x  = lo32(mx[k]);
            float y  = lo32(my2[k]);
            float z  = lo32(mz2[k]);
            float sq = -2.0f * lo32(mh[k]);    // exact
            float cmp = CUT2 - sq;
            int iloc = iloc0 + k * PT_THREADS;

            float t0 = z * Bv.x;
            t0 = fmaf(y, A.z, t0);
            t0 = fmaf(x, A.x, t0);
            float d20 = fmaf(-2.0f, t0, w0);
            if (d20 <= cmp && (!diag || iloc > jl0)) {
                float d = sqrtf(fmaxf(d20 + sq, 0.0f) + 1e-12f);
                sum[k] += d;
                atomicAdd(&shj[2 * jjl], d);
            }

            float t1 = z * Bv.y;
            t1 = fmaf(y, A.w, t1);
            t1 = fmaf(x, A.y, t1);
            float d21 = fmaf(-2.0f, t1, w1);
            if (d21 <= cmp && (!diag || iloc > jl0 + 1)) {
                float d = sqrtf(fmaxf(d21 + sq, 0.0f) + 1e-12f);
                sum[k] += d;
                atomicAdd(&shj[2 * jjl + 1], d);
            }
        }
    }

    // ---- write partials ----
    #pragma unroll
    for (int k = 0; k < RPT; k++)
        g_ip[c * NTOT + row0g + k * PT_THREADS] = sum[k];
    __syncthreads();                   // shj atomics complete
    if (tid < 64)
        g_jp[r * NTOT + jbase + tid] = shj[tid];
}

// ---------------------------------------------------------------------------
// Kernel 2: deterministic 4-thread-per-row reduce -> out col 1
//   part p sums i-tiles c≡p (mod 4), c<8r+8 and j-tiles rp≡p (mod 4), rp>=r;
//   fixed shuffle tree ((p0+p1)+(p2+p3)); + self term sqrt(1e-12) if valid.
// ---------------------------------------------------------------------------
#define RED_THREADS 256
#define RED_ROWS (RED_THREADS / 4)          // 64 rows per block

__global__ void __launch_bounds__(RED_THREADS)
ff_reduce(const float* __restrict__ coords,
          const int*   __restrict__ abatch,
          const int*   __restrict__ cidx,
          float*       __restrict__ out) {
    int tid  = threadIdx.x;
    int row  = blockIdx.x * RED_ROWS + (tid >> 2);
    int part = tid & 3;
    int loc  = row & (MPER - 1);
    int r    = loc >> 9;
    int cmax = 8 * r + 8;

    float s = 0.0f;
    #pragma unroll 4
    for (int c = part; c < cmax; c += 4)
        s += g_ip[c * NTOT + row];
    #pragma unroll
    for (int rp = part; rp < 8; rp += 4)
        if (rp >= r) s += g_jp[rp * NTOT + row];

    // fixed-tree combine across the 4 parts (lanes 4q..4q+3)
    s += __shfl_down_sync(0xffffffffu, s, 1);
    s += __shfl_down_sync(0xffffffffu, s, 2);

    if (part == 0) {
        const float* p = coords + ((long)abatch[row] * MPER + cidx[row]) * 3;
        if (p[0] != PAD_F) s += sqrtf(1e-12f);   // self pair
        else               s = 0.0f;             // invalid row: empty sum
        out[(long)row * 8 + 1] = s;
    }
}

// ---------------------------------------------------------------------------
extern "C" void kernel_launch(void* const* d_in, const int* in_sizes, int n_in,
                              void* d_out, int out_size) {
    const float* coords   = (const float*)d_in[0];
    const int*   abatch   = (const int*)  d_in[1];
    const int*   cidx     = (const int*)  d_in[2];
    const int*   partners = (const int*)  d_in[3];
    const int*   aidx     = (const int*)  d_in[4];
    float*       out      = (float*)d_out;

    ff_main<<<NBLOCKS, PT_THREADS>>>(coords, abatch, cidx, partners, aidx, out);
    ff_reduce<<<NTOT / RED_ROWS, RED_THREADS>>>(coords, abatch, cidx, out);
}